// round 1
// baseline (speedup 1.0000x reference)
#include <cuda_runtime.h>
#include <cstdint>

// ---------------------------------------------------------------------------
// StatelessMambaDecoder: fp32 baseline
//   x = z_seq @ ip_w.T + ip_b
//   2x { LN -> inproj GEMM (split xp/z) -> causal depthwise conv+SiLU ->
//        xproj GEMM (B,C,dt_raw) -> dt=softplus -> selective scan ->
//        (y*silu(z)) @ outproj.T + residual }
//   final LN -> head GEMV (OUT=2)
// ---------------------------------------------------------------------------

#define NFULL 0xffffffffu

namespace {
constexpr int BB   = 8;
constexpr int SS   = 4096;
constexpr int DM   = 256;
constexpr int DI   = 512;
constexpr int DS   = 16;
constexpr int MT   = BB * SS;   // 32768 tokens
constexpr float EPSV = 1e-5f;
}

// scratch (static device globals; allocation-free per harness rules)
__device__ float g_x    [MT * DM];   // residual stream
__device__ float g_xn   [MT * DM];   // layernorm output
__device__ float g_xp   [MT * DI];   // inproj half 1
__device__ float g_z    [MT * DI];   // inproj half 2 (gate)
__device__ float g_xc   [MT * DI];   // conv+silu output
__device__ float g_dt   [MT * DI];   // softplus(dt)
__device__ float g_y    [MT * DI];   // scan output
__device__ float g_Bm   [MT * DS];
__device__ float g_Cm   [MT * DS];
__device__ float g_dtraw[MT];

__device__ __forceinline__ float siluf(float x) {
    return x / (1.f + __expf(-x));
}

// -------------------------------------------------------------------- inproj
__global__ void k_inproj(const float* __restrict__ z,
                         const float* __restrict__ w,
                         const float* __restrict__ b) {
    int idx = blockIdx.x * blockDim.x + threadIdx.x;
    if (idx >= MT * DM) return;
    int m = idx / DM, c = idx % DM;
    float4 zv = *reinterpret_cast<const float4*>(z + (size_t)m * 4);
    float4 wv = *reinterpret_cast<const float4*>(w + (size_t)c * 4);
    g_x[idx] = b[c] + zv.x * wv.x + zv.y * wv.y + zv.z * wv.z + zv.w * wv.w;
}

// ----------------------------------------------------------------- layernorm
__global__ void k_ln(const float* __restrict__ g, const float* __restrict__ b) {
    int warp = (blockIdx.x * blockDim.x + threadIdx.x) >> 5;
    int lane = threadIdx.x & 31;
    if (warp >= MT) return;
    const float* xr = g_x + (size_t)warp * DM;
    float v[8];
    float s = 0.f;
#pragma unroll
    for (int i = 0; i < 8; i++) { v[i] = xr[i * 32 + lane]; s += v[i]; }
#pragma unroll
    for (int o = 16; o; o >>= 1) s += __shfl_xor_sync(NFULL, s, o);
    float mu = s * (1.f / DM);
    float q = 0.f;
#pragma unroll
    for (int i = 0; i < 8; i++) { float d = v[i] - mu; q += d * d; }
#pragma unroll
    for (int o = 16; o; o >>= 1) q += __shfl_xor_sync(NFULL, q, o);
    float r = rsqrtf(q * (1.f / DM) + EPSV);
    float* out = g_xn + (size_t)warp * DM;
#pragma unroll
    for (int i = 0; i < 8; i++) {
        int c = i * 32 + lane;
        out[c] = (v[i] - mu) * r * g[c] + b[c];
    }
}

// ------------------------------------------------------------------- GEMM
// C(MT x N) = A(MT x K) * W^T   (W: N x K, row-major). 128x128x8 tiles.
// MODE 0: A = g_xn (K=256), N=1024 -> cols<512 to g_xp, cols>=512 to g_z
// MODE 1: A = g_y * silu(g_z) (K=512), N=256 -> g_x += result (residual)
template <int MODE>
__global__ __launch_bounds__(256)
void k_gemm(const float* __restrict__ W) {
    constexpr int K = (MODE == 0) ? DM : DI;
    __shared__ float As[8][128];
    __shared__ float Bs[8][128];
    const int tid = threadIdx.x;
    const int mBase = blockIdx.y * 128;
    const int nBase = blockIdx.x * 128;
    const int lr = tid >> 1;           // 0..127
    const int lc = (tid & 1) * 4;      // 0 or 4
    const int tx = tid & 15;
    const int ty = tid >> 4;

    const float* Aptr = (MODE == 0) ? g_xn : g_y;

    float acc[8][8];
#pragma unroll
    for (int i = 0; i < 8; i++)
#pragma unroll
        for (int j = 0; j < 8; j++) acc[i][j] = 0.f;

    auto loadA = [&](int k0) -> float4 {
        float4 a = *reinterpret_cast<const float4*>(
            Aptr + (size_t)(mBase + lr) * K + k0 + lc);
        if (MODE == 1) {
            float4 zv = *reinterpret_cast<const float4*>(
                g_z + (size_t)(mBase + lr) * K + k0 + lc);
            a.x *= siluf(zv.x); a.y *= siluf(zv.y);
            a.z *= siluf(zv.z); a.w *= siluf(zv.w);
        }
        return a;
    };
    auto loadB = [&](int k0) -> float4 {
        return *reinterpret_cast<const float4*>(
            W + (size_t)(nBase + lr) * K + k0 + lc);
    };

    float4 av = loadA(0);
    float4 bv = loadB(0);
    for (int k0 = 0; k0 < K; k0 += 8) {
        As[lc + 0][lr] = av.x; As[lc + 1][lr] = av.y;
        As[lc + 2][lr] = av.z; As[lc + 3][lr] = av.w;
        Bs[lc + 0][lr] = bv.x; Bs[lc + 1][lr] = bv.y;
        Bs[lc + 2][lr] = bv.z; Bs[lc + 3][lr] = bv.w;
        __syncthreads();
        if (k0 + 8 < K) { av = loadA(k0 + 8); bv = loadB(k0 + 8); }
#pragma unroll
        for (int kk = 0; kk < 8; kk++) {
            float af[8], bf[8];
            *reinterpret_cast<float4*>(af)     = *reinterpret_cast<const float4*>(&As[kk][ty * 4]);
            *reinterpret_cast<float4*>(af + 4) = *reinterpret_cast<const float4*>(&As[kk][64 + ty * 4]);
            *reinterpret_cast<float4*>(bf)     = *reinterpret_cast<const float4*>(&Bs[kk][tx * 4]);
            *reinterpret_cast<float4*>(bf + 4) = *reinterpret_cast<const float4*>(&Bs[kk][64 + tx * 4]);
#pragma unroll
            for (int i = 0; i < 8; i++)
#pragma unroll
                for (int j = 0; j < 8; j++)
                    acc[i][j] += af[i] * bf[j];
        }
        __syncthreads();
    }

#pragma unroll
    for (int i = 0; i < 8; i++) {
        int row = mBase + ((i < 4) ? (ty * 4 + i) : (64 + ty * 4 + i - 4));
#pragma unroll
        for (int j = 0; j < 8; j++) {
            int col = nBase + ((j < 4) ? (tx * 4 + j) : (64 + tx * 4 + j - 4));
            float v = acc[i][j];
            if (MODE == 0) {
                if (col < DI) g_xp[(size_t)row * DI + col] = v;
                else          g_z [(size_t)row * DI + col - DI] = v;
            } else {
                size_t o = (size_t)row * DM + col;
                g_x[o] += v;   // residual add
            }
        }
    }
}

// ----------------------------------------------------- depthwise conv + SiLU
__global__ void k_conv(const float* __restrict__ cw, const float* __restrict__ cb) {
    int idx = blockIdx.x * blockDim.x + threadIdx.x;
    if (idx >= MT * DI) return;
    int d = idx % DI;
    int m = idx / DI;
    int t = m & (SS - 1);
    float acc = cb[d];
#pragma unroll
    for (int j = 0; j < 4; j++) {
        int tt = t - 3 + j;
        if (tt >= 0) acc += g_xp[idx + (j - 3) * DI] * cw[d * 4 + j];
    }
    g_xc[idx] = siluf(acc);
}

// --------------------------------------------------------- xproj (N=33 GEMV)
__global__ void k_xproj(const float* __restrict__ Wx) {
    int warp = (blockIdx.x * blockDim.x + threadIdx.x) >> 5;
    int lane = threadIdx.x & 31;
    if (warp >= MT) return;
    const float* xr = g_xc + (size_t)warp * DI;
    float v[16];
#pragma unroll
    for (int i = 0; i < 16; i++) v[i] = xr[i * 32 + lane];
    for (int n = 0; n < 2 * DS + 1; n++) {
        const float* w = Wx + (size_t)n * DI;
        float acc = 0.f;
#pragma unroll
        for (int i = 0; i < 16; i++) acc += v[i] * w[i * 32 + lane];
#pragma unroll
        for (int o = 16; o; o >>= 1) acc += __shfl_xor_sync(NFULL, acc, o);
        if (lane == 0) {
            if (n < DS)          g_Bm[(size_t)warp * DS + n] = acc;
            else if (n < 2 * DS) g_Cm[(size_t)warp * DS + n - DS] = acc;
            else                 g_dtraw[warp] = acc;
        }
    }
}

// --------------------------------------------------------------- dt softplus
__global__ void k_dt(const float* __restrict__ dw, const float* __restrict__ db) {
    int idx = blockIdx.x * blockDim.x + threadIdx.x;
    if (idx >= MT * DI) return;
    int d = idx % DI, m = idx / DI;
    float x = g_dtraw[m] * dw[d] + db[d];
    g_dt[idx] = fmaxf(x, 0.f) + log1pf(__expf(-fabsf(x)));
}

// ----------------------------------------------------------- selective scan
// One 16-lane group per (batch, d_inner) channel; lane = state index s-1.
__global__ void k_scan() {
    int gid = (blockIdx.x * blockDim.x + threadIdx.x) >> 4;
    int l16 = threadIdx.x & 15;
    if (gid >= BB * DI) return;
    int b = gid / DI, d = gid % DI;
    const float s = (float)(l16 + 1);
    float h = 0.f;
    const float* dtp = g_dt + (size_t)b * SS * DI + d;
    const float* xpp = g_xc + (size_t)b * SS * DI + d;
    const float* Bp  = g_Bm + (size_t)b * SS * DS + l16;
    const float* Cp  = g_Cm + (size_t)b * SS * DS + l16;
    float* yp        = g_y  + (size_t)b * SS * DI + d;
    for (int t = 0; t < SS; t++) {
        float dtv = dtp[(size_t)t * DI];
        float xv  = xpp[(size_t)t * DI];
        float Bs  = Bp[(size_t)t * DS];
        float Cs  = Cp[(size_t)t * DS];
        float ab  = __expf(-s * dtv);
        h = ab * h + (dtv * xv) * Bs;
        float c = h * Cs;
#pragma unroll
        for (int o = 8; o; o >>= 1) c += __shfl_xor_sync(NFULL, c, o);
        if (l16 == 0) yp[(size_t)t * DI] = c;
    }
}

// --------------------------------------------------------- final LN + head
__global__ void k_final(const float* __restrict__ g, const float* __restrict__ b,
                        const float* __restrict__ ow, const float* __restrict__ ob,
                        float* __restrict__ out) {
    int warp = (blockIdx.x * blockDim.x + threadIdx.x) >> 5;
    int lane = threadIdx.x & 31;
    if (warp >= MT) return;
    const float* xr = g_x + (size_t)warp * DM;
    float v[8];
    float s = 0.f;
#pragma unroll
    for (int i = 0; i < 8; i++) { v[i] = xr[i * 32 + lane]; s += v[i]; }
#pragma unroll
    for (int o = 16; o; o >>= 1) s += __shfl_xor_sync(NFULL, s, o);
    float mu = s * (1.f / DM);
    float q = 0.f;
#pragma unroll
    for (int i = 0; i < 8; i++) { float d = v[i] - mu; q += d * d; }
#pragma unroll
    for (int o = 16; o; o >>= 1) q += __shfl_xor_sync(NFULL, q, o);
    float r = rsqrtf(q * (1.f / DM) + EPSV);
    float a0 = 0.f, a1 = 0.f;
#pragma unroll
    for (int i = 0; i < 8; i++) {
        int c = i * 32 + lane;
        float xn = (v[i] - mu) * r * g[c] + b[c];
        a0 += xn * ow[c];
        a1 += xn * ow[DM + c];
    }
#pragma unroll
    for (int o = 16; o; o >>= 1) {
        a0 += __shfl_xor_sync(NFULL, a0, o);
        a1 += __shfl_xor_sync(NFULL, a1, o);
    }
    if (lane == 0) {
        out[(size_t)warp * 2 + 0] = a0 + ob[0];
        out[(size_t)warp * 2 + 1] = a1 + ob[1];
    }
}

// ---------------------------------------------------------------------------
extern "C" void kernel_launch(void* const* d_in, const int* in_sizes, int n_in,
                              void* d_out, int out_size) {
    (void)in_sizes; (void)n_in; (void)out_size;
    const float* z_seq     = (const float*)d_in[0];
    const float* ip_w      = (const float*)d_in[1];
    const float* ip_b      = (const float*)d_in[2];
    const float* norm_g    = (const float*)d_in[3];
    const float* norm_b    = (const float*)d_in[4];
    const float* inproj_w  = (const float*)d_in[5];
    const float* conv_w    = (const float*)d_in[6];
    const float* conv_b    = (const float*)d_in[7];
    const float* xproj_w   = (const float*)d_in[8];
    const float* dt_w      = (const float*)d_in[9];
    const float* dt_b      = (const float*)d_in[10];
    const float* outproj_w = (const float*)d_in[11];
    const float* onorm_g   = (const float*)d_in[12];
    const float* onorm_b   = (const float*)d_in[13];
    const float* op_w      = (const float*)d_in[14];
    const float* op_b      = (const float*)d_in[15];
    float* out = (float*)d_out;

    k_inproj<<<MT * DM / 256, 256>>>(z_seq, ip_w, ip_b);

    for (int l = 0; l < 2; l++) {
        k_ln<<<MT / 8, 256>>>(norm_g + l * DM, norm_b + l * DM);
        k_gemm<0><<<dim3(2 * DI / 128, MT / 128), 256>>>(
            inproj_w + (size_t)l * 2 * DI * DM);
        k_conv<<<MT * DI / 256, 256>>>(conv_w + (size_t)l * DI * 4,
                                       conv_b + (size_t)l * DI);
        k_xproj<<<MT / 8, 256>>>(xproj_w + (size_t)l * (2 * DS + 1) * DI);
        k_dt<<<MT * DI / 256, 256>>>(dt_w + (size_t)l * DI, dt_b + (size_t)l * DI);
        k_scan<<<(BB * DI * 16) / 256, 256>>>();
        k_gemm<1><<<dim3(DM / 128, MT / 128), 256>>>(
            outproj_w + (size_t)l * DM * DI);
    }

    k_final<<<MT / 8, 256>>>(onorm_g, onorm_b, op_w, op_b, out);
}